// round 10
// baseline (speedup 1.0000x reference)
#include <cuda_runtime.h>
#include <math.h>

#define T    128
#define D    64
#define H    256
#define HK   128
#define DD   (D*D)
#define ITERS 3
#define NB   128
#define NT   1024
#define NSLOT 128
#define NBAR 16
#define NLEAF 16

// ---- scratch (static device globals; no runtime allocation) ----
__device__ float A3_g[HK*T*T];         // 8 MB  A3[h][j][i] = w_ij * tanh(...)
__device__ float W2T_g[HK*DD];         // 2 MB  [h][e][d]
__device__ float bk2T_g[DD];           //       [e][d]
__device__ float fyT_g[D*T];           //       f(y) transposed: [e][j]
__device__ float c_g[T*D];
__device__ float Gpart_g[NSLOT*T*D];   // 4 MB  slot = h
__device__ float G_g[T*D];

// hierarchical grid barrier (replay-safe: last root-departer resets all)
__device__ unsigned lfA[NBAR][NLEAF];
__device__ unsigned rtA[NBAR];
__device__ unsigned lfD[NBAR][NLEAF];
__device__ unsigned rtD[NBAR];

__device__ __forceinline__ void gsync(int b) {
    __syncthreads();
    if (threadIdx.x == 0) {
        __threadfence();
        int leaf = blockIdx.x & (NLEAF - 1);
        if (atomicAdd(&lfA[b][leaf], 1u) == 7u)
            atomicAdd(&rtA[b], 1u);
        while (*(volatile unsigned*)&rtA[b] < (unsigned)NLEAF) { }
        __threadfence();
        if (atomicAdd(&lfD[b][leaf], 1u) == 7u) {
            if (atomicAdd(&rtD[b], 1u) == (unsigned)(NLEAF - 1)) {
                #pragma unroll
                for (int l = 0; l < NLEAF; l++) { lfA[b][l] = 0u; lfD[b][l] = 0u; }
                rtA[b] = 0u;
                __threadfence();
                rtD[b] = 0u;
            }
        }
    }
    __syncthreads();
}

// trapezoid weight w[i][j]: w = dt*(j<=i); w[i,i]*=0.5; w[:,0]*=0.5; w[0,:]=0
__device__ __forceinline__ float wfun(int i, int j, float dt) {
    if (i == 0 || j > i) return 0.0f;
    float v = dt;
    if (j == i) v *= 0.5f;
    if (j == 0) v *= 0.5f;
    return v;
}

__global__ void __launch_bounds__(NT, 1) mega(
    const float* __restrict__ z0, const float* __restrict__ t,
    const float* __restrict__ W1, const float* __restrict__ b1,
    const float* __restrict__ W2, const float* __restrict__ b2,
    const float* __restrict__ Wk1, const float* __restrict__ bk1,
    const float* __restrict__ Wk2, const float* __restrict__ bk2,
    float* __restrict__ out)
{
    // dynamic smem: w2s[4096] | a3c[4096] | fyc/exch[2048] | m3c[2048]  = 48 KB
    extern __shared__ float sbuf[];
    float* w2s = sbuf;
    float* a3c = sbuf + 4096;
    float* fyc = sbuf + 8192;       // doubles as partial-exchange buffer
    float* m3c = sbuf + 10240;
    __shared__ float ts[T];
    __shared__ float yrow[D], hid[H], fyr[D];
    __shared__ float part16[16][D];
    __shared__ float hidpart[4][H];

    int bid = blockIdx.x, tid = threadIdx.x;

    // ================= SETUP =================
    // W2T[h=bid][e][d] = Wk2[h][d*64+e] via padded smem transpose (use a3c+fyc area)
    {
        float* tr = sbuf + 4096;    // 67*64 = 4288 floats fits in a3c+fyc
        #pragma unroll
        for (int r = 0; r < 4; r++) {
            int idx = tid + r * 1024;
            tr[(idx >> 6) * 67 + (idx & 63)] = Wk2[bid * DD + idx];
        }
        __syncthreads();
        #pragma unroll
        for (int r = 0; r < 4; r++) {
            int idx = tid + r * 1024;
            W2T_g[bid * DD + idx] = tr[(idx & 63) * 67 + (idx >> 6)];
        }
        __syncthreads();
        if (bid == 0) {            // bk2T (block-uniform branch)
            #pragma unroll
            for (int r = 0; r < 4; r++) {
                int idx = tid + r * 1024;
                tr[(idx >> 6) * 67 + (idx & 63)] = bk2[idx];
            }
            __syncthreads();
            #pragma unroll
            for (int r = 0; r < 4; r++) {
                int idx = tid + r * 1024;
                bk2T_g[idx] = tr[(idx & 63) * 67 + (idx >> 6)];
            }
        }
    }
    if (tid < T) ts[tid] = t[tid];
    __syncthreads();
    float dt = ts[1] - ts[0];
    // A3[h=bid][j][i], coalesced over i
    {
        float wah = Wk1[bid], wbh = Wk1[HK + bid], bkh = bk1[bid];
        #pragma unroll 4
        for (int r = 0; r < 16; r++) {
            int idx = tid + r * 1024;              // j = idx>>7, i = idx&127
            int j = idx >> 7, i = idx & 127;
            float v = tanhf(ts[i] * wah + ts[j] * wbh + bkh);
            A3_g[bid * (T * T) + idx] = wfun(i, j, dt) * v;
        }
    }

    int bar = 0;
    gsync(bar++);

    // ================= FIXED-POINT ITERATIONS =================
    for (int it = 0; it < ITERS; it++) {
        // ---- phase F (block j): y_j = y0 + (w@G)_j (fused), then fy[j], c[j] ----
        {
            int j = bid;
            int d = tid & 63, p = tid >> 6;        // 16-way split
            if (it == 0) {
                if (tid < D) yrow[tid] = z0[tid];
            } else {
                float s = 0.0f;
                for (int i = p; i <= j; i += 16)
                    s += wfun(j, i, dt) * __ldcg(&G_g[i * D + d]);
                part16[p][d] = s;
                __syncthreads();
                if (p == 0) {
                    float acc = z0[d];
                    #pragma unroll
                    for (int r = 0; r < 16; r++) acc += part16[r][d];
                    yrow[d] = acc;
                }
            }
            __syncthreads();
            {
                int h = tid & 255, q = tid >> 8;
                float s = (q == 0) ? b1[h] : 0.0f;
                #pragma unroll
                for (int ee = 0; ee < 16; ee++) {
                    int e = q * 16 + ee;
                    s += yrow[e] * W1[e * H + h];
                }
                hidpart[q][h] = s;
            }
            __syncthreads();
            if (tid < H)
                hid[tid] = tanhf(hidpart[0][tid] + hidpart[1][tid] + hidpart[2][tid] + hidpart[3][tid]);
            __syncthreads();
            {
                float s = 0.0f;
                #pragma unroll
                for (int hh = 0; hh < 16; hh++) {
                    int h = p * 16 + hh;
                    s += hid[h] * W2[h * D + d];
                }
                part16[p][d] = s;
            }
            __syncthreads();
            if (p == 0) {
                float f = b2[d];
                #pragma unroll
                for (int r = 0; r < 16; r++) f += part16[r][d];
                fyr[d] = f;
                fyT_g[d * T + j] = f;              // [e][j]
            }
            __syncthreads();
            {
                float s = 0.0f;
                #pragma unroll
                for (int ee = 0; ee < 4; ee++) {
                    int e = p * 4 + ee;
                    s += bk2T_g[e * D + d] * fyr[e];
                }
                part16[p][d] = s;
            }
            __syncthreads();
            if (p == 0) {
                float cc = 0.0f;
                #pragma unroll
                for (int r = 0; r < 16; r++) cc += part16[r][d];
                c_g[j * D + d] = cc;
            }
        }
        gsync(bar++);

        // ---- phase MG (block h): m3 for j-chunk, then G-accumulate; pipelined ----
        {
            int h = bid;
            // load w2s once per iteration
            #pragma unroll
            for (int r = 0; r < 4; r++)
                w2s[tid + r * 1024] = W2T_g[h * DD + tid + r * 1024];

            // prefetch chunk 0
            float4 a3n; float2 fyn;
            {
                int j = tid >> 5, i4 = tid & 31;
                a3n = *(const float4*)&A3_g[(h * T + j) * T + i4 * 4];
                int e = tid >> 4, jj2 = (tid & 15) * 2;
                fyn = *(const float2*)&fyT_g[e * T + jj2];
            }

            // G accumulators: thread (gx = d4, gy = i-pair)
            int gx = tid & 15, gy = tid >> 4;
            int i2 = gy * 2;
            float ga[2][4] = {};

            // m3 mapping: tx = d4, jt = j, p = e-half
            int tx = tid & 15, jt = (tid >> 4) & 31, p2 = tid >> 9;

            for (int cb = 0; cb < 4; cb++) {
                int j0 = cb * 32;
                __syncthreads();                       // prev chunk smem free
                ((float4*)a3c)[tid] = a3n;
                ((float2*)fyc)[tid] = fyn;
                __syncthreads();
                if (cb < 3) {                           // prefetch next chunk
                    int j0n = j0 + 32;
                    int j = tid >> 5, i4 = tid & 31;
                    a3n = *(const float4*)&A3_g[(h * T + j0n + j) * T + i4 * 4];
                    int e = tid >> 4, jj2 = (tid & 15) * 2;
                    fyn = *(const float2*)&fyT_g[e * T + j0n + jj2];
                }
                // m3 partial: acc over 32 e (half p2)
                float m0 = 0.f, m1 = 0.f, m2 = 0.f, m3v = 0.f;
                {
                    int ebase = p2 * 32;
                    #pragma unroll
                    for (int ee = 0; ee < 32; ee++) {
                        int e = ebase + ee;
                        float4 w4 = *(const float4*)&w2s[e * 64 + tx * 4];
                        float f = fyc[e * 32 + jt];
                        m0 += f * w4.x; m1 += f * w4.y; m2 += f * w4.z; m3v += f * w4.w;
                    }
                }
                __syncthreads();                       // fyc reads done
                if (p2 == 1)                            // exchange via fyc space
                    *(float4*)&fyc[jt * 64 + tx * 4] = make_float4(m0, m1, m2, m3v);
                __syncthreads();
                if (p2 == 0) {
                    float4 o = *(const float4*)&fyc[jt * 64 + tx * 4];
                    o.x += m0; o.y += m1; o.z += m2; o.w += m3v;
                    *(float4*)&m3c[jt * 64 + tx * 4] = o;
                }
                __syncthreads();                       // m3c ready
                // G accumulate (triangular bound: only j0+j <= i2+1 contributes)
                int jmax = i2 + 2 - j0; if (jmax > 32) jmax = 32;
                for (int j = 0; j < jmax; j++) {
                    float2 a = *(const float2*)&a3c[j * 128 + i2];
                    float4 b = *(const float4*)&m3c[j * 64 + gx * 4];
                    ga[0][0] += a.x * b.x; ga[0][1] += a.x * b.y;
                    ga[0][2] += a.x * b.z; ga[0][3] += a.x * b.w;
                    ga[1][0] += a.y * b.x; ga[1][1] += a.y * b.y;
                    ga[1][2] += a.y * b.z; ga[1][3] += a.y * b.w;
                }
            }
            // store Gpart[h]
            float* gp = &Gpart_g[h * (T * D)];
            #pragma unroll
            for (int r = 0; r < 2; r++) {
                float4 o = make_float4(ga[r][0], ga[r][1], ga[r][2], ga[r][3]);
                *(float4*)&gp[(i2 + r) * D + gx * 4] = o;
            }
        }
        gsync(bar++);

        // ---- phase R (block i): reduce 128 h-slots + bias quadrature -> G ----
        {
            int i = bid;
            int d = tid & 63, p = tid >> 6;        // 16-way
            float s = 0.0f;
            #pragma unroll
            for (int sl = p; sl < NSLOT; sl += 16)
                s += __ldcg(&Gpart_g[sl * (T * D) + i * D + d]);
            for (int jj = p; jj <= i; jj += 16)
                s += wfun(i, jj, dt) * __ldcg(&c_g[jj * D + d]);
            part16[p][d] = s;
            __syncthreads();
            if (p == 0) {
                float acc = 0.0f;
                #pragma unroll
                for (int r = 0; r < 16; r++) acc += part16[r][d];
                G_g[i * D + d] = acc;
            }
        }
        gsync(bar++);
    }

    // ---- tail: block 127 computes out = y0 + (w@G)_{127} ----
    if (bid == T - 1) {
        int d = tid & 63, p = tid >> 6;
        float s = 0.0f;
        for (int i = p; i < T; i += 16)
            s += wfun(T - 1, i, dt) * __ldcg(&G_g[i * D + d]);
        part16[p][d] = s;
        __syncthreads();
        if (p == 0) {
            float acc = z0[d];
            #pragma unroll
            for (int r = 0; r < 16; r++) acc += part16[r][d];
            out[d] = acc;
        }
    }
}

extern "C" void kernel_launch(void* const* d_in, const int* in_sizes, int n_in,
                              void* d_out, int out_size) {
    const float* z0  = (const float*)d_in[0];
    const float* t   = (const float*)d_in[1];
    const float* W1  = (const float*)d_in[2];
    const float* b1  = (const float*)d_in[3];
    const float* W2  = (const float*)d_in[4];
    const float* b2  = (const float*)d_in[5];
    const float* Wk1 = (const float*)d_in[6];
    const float* bk1 = (const float*)d_in[7];
    const float* Wk2 = (const float*)d_in[8];
    const float* bk2 = (const float*)d_in[9];
    float* out = (float*)d_out;

    static int attr_done = 0;
    if (!attr_done) {
        cudaFuncSetAttribute(mega, cudaFuncAttributeMaxDynamicSharedMemorySize, 64 * 1024);
        attr_done = 1;
    }
    mega<<<NB, NT, 49152>>>(z0, t, W1, b1, W2, b2, Wk1, bk1, Wk2, bk2, out);
}

// round 11
// speedup vs baseline: 1.0807x; 1.0807x over previous
#include <cuda_runtime.h>
#include <math.h>

#define T    128
#define D    64
#define H    256
#define HK   128
#define DD   (D*D)
#define ITERS 3
#define NB   128
#define NT   1024
#define NSLOT 128
#define NBAR 16
#define NLEAF 16

// ---- scratch (static device globals; no runtime allocation) ----
__device__ float A3_g[HK*T*T];         // 8 MB  A3[h][j][i] = w_ij * tanh(...)
__device__ float W2T_g[HK*DD];         // 2 MB  [h][e][d]
__device__ float bk2T_g[DD];           //       [e][d]
__device__ float fy_g[T*D];            //       f(y): [j][e]
__device__ float c_g[T*D];
__device__ float Gpart_g[NSLOT*T*D];   // 4 MB  slot = h
__device__ float G_g[T*D];

// hierarchical grid barrier (replay-safe: last root-departer resets all)
__device__ unsigned lfA[NBAR][NLEAF];
__device__ unsigned rtA[NBAR];
__device__ unsigned lfD[NBAR][NLEAF];
__device__ unsigned rtD[NBAR];

__device__ __forceinline__ void gsync(int b) {
    __syncthreads();
    if (threadIdx.x == 0) {
        __threadfence();
        int leaf = blockIdx.x & (NLEAF - 1);
        if (atomicAdd(&lfA[b][leaf], 1u) == 7u)
            atomicAdd(&rtA[b], 1u);
        while (*(volatile unsigned*)&rtA[b] < (unsigned)NLEAF) { }
        __threadfence();
        if (atomicAdd(&lfD[b][leaf], 1u) == 7u) {
            if (atomicAdd(&rtD[b], 1u) == (unsigned)(NLEAF - 1)) {
                #pragma unroll
                for (int l = 0; l < NLEAF; l++) { lfA[b][l] = 0u; lfD[b][l] = 0u; }
                rtA[b] = 0u;
                __threadfence();
                rtD[b] = 0u;
            }
        }
    }
    __syncthreads();
}

// trapezoid weight w[i][j]: w = dt*(j<=i); w[i,i]*=0.5; w[:,0]*=0.5; w[0,:]=0
__device__ __forceinline__ float wfun(int i, int j, float dt) {
    if (i == 0 || j > i) return 0.0f;
    float v = dt;
    if (j == i) v *= 0.5f;
    if (j == 0) v *= 0.5f;
    return v;
}

__global__ void __launch_bounds__(NT, 1) mega(
    const float* __restrict__ z0, const float* __restrict__ t,
    const float* __restrict__ W1, const float* __restrict__ b1,
    const float* __restrict__ W2, const float* __restrict__ b2,
    const float* __restrict__ Wk1, const float* __restrict__ bk1,
    const float* __restrict__ Wk2, const float* __restrict__ bk2,
    float* __restrict__ out)
{
    // dynamic smem 48 KB: w2s[4096] | a3c[4096] | m3c0[2048] | m3c1[2048]
    extern __shared__ float sbuf[];
    float* w2s = sbuf;
    float* a3c = sbuf + 4096;
    __shared__ float ts[T];
    __shared__ float yrow[D], hid[H], fyr[D];
    __shared__ float part16[16][D];
    __shared__ float hidpart[4][H];

    int bid = blockIdx.x, tid = threadIdx.x;

    // ================= SETUP =================
    // W2T[h=bid][e][d] = Wk2[h][d*64+e] via padded smem transpose (scratch = a3c area)
    {
        float* tr = sbuf + 4096;    // 67*64 = 4288 floats
        #pragma unroll
        for (int r = 0; r < 4; r++) {
            int idx = tid + r * 1024;
            tr[(idx >> 6) * 67 + (idx & 63)] = Wk2[bid * DD + idx];
        }
        __syncthreads();
        #pragma unroll
        for (int r = 0; r < 4; r++) {
            int idx = tid + r * 1024;
            W2T_g[bid * DD + idx] = tr[(idx & 63) * 67 + (idx >> 6)];
        }
        __syncthreads();
        if (bid == 0) {            // bk2T (block-uniform branch)
            #pragma unroll
            for (int r = 0; r < 4; r++) {
                int idx = tid + r * 1024;
                tr[(idx >> 6) * 67 + (idx & 63)] = bk2[idx];
            }
            __syncthreads();
            #pragma unroll
            for (int r = 0; r < 4; r++) {
                int idx = tid + r * 1024;
                bk2T_g[idx] = tr[(idx & 63) * 67 + (idx >> 6)];
            }
        }
    }
    if (tid < T) ts[tid] = t[tid];
    __syncthreads();
    float dt = ts[1] - ts[0];
    // A3[h=bid][j][i], coalesced over i
    {
        float wah = Wk1[bid], wbh = Wk1[HK + bid], bkh = bk1[bid];
        #pragma unroll 4
        for (int r = 0; r < 16; r++) {
            int idx = tid + r * 1024;              // j = idx>>7, i = idx&127
            int j = idx >> 7, i = idx & 127;
            float v = tanhf(ts[i] * wah + ts[j] * wbh + bkh);
            A3_g[bid * (T * T) + idx] = wfun(i, j, dt) * v;
        }
    }

    int bar = 0;
    gsync(bar++);

    // ================= FIXED-POINT ITERATIONS =================
    for (int it = 0; it < ITERS; it++) {
        // ---- phase F (block j): y_j = y0 + (w@G)_j (fused), then fy[j], c[j] ----
        {
            int j = bid;
            int d = tid & 63, p = tid >> 6;        // 16-way split
            if (it == 0) {
                if (tid < D) yrow[tid] = z0[tid];
            } else {
                float s = 0.0f;
                for (int i = p; i <= j; i += 16)
                    s += wfun(j, i, dt) * __ldcg(&G_g[i * D + d]);
                part16[p][d] = s;
                __syncthreads();
                if (p == 0) {
                    float acc = z0[d];
                    #pragma unroll
                    for (int r = 0; r < 16; r++) acc += part16[r][d];
                    yrow[d] = acc;
                }
            }
            __syncthreads();
            {
                int h = tid & 255, q = tid >> 8;
                float s = (q == 0) ? b1[h] : 0.0f;
                #pragma unroll
                for (int ee = 0; ee < 16; ee++) {
                    int e = q * 16 + ee;
                    s += yrow[e] * W1[e * H + h];
                }
                hidpart[q][h] = s;
            }
            __syncthreads();
            if (tid < H)
                hid[tid] = tanhf(hidpart[0][tid] + hidpart[1][tid] + hidpart[2][tid] + hidpart[3][tid]);
            __syncthreads();
            {
                float s = 0.0f;
                #pragma unroll
                for (int hh = 0; hh < 16; hh++) {
                    int h = p * 16 + hh;
                    s += hid[h] * W2[h * D + d];
                }
                part16[p][d] = s;
            }
            __syncthreads();
            if (p == 0) {
                float f = b2[d];
                #pragma unroll
                for (int r = 0; r < 16; r++) f += part16[r][d];
                fyr[d] = f;
                fy_g[j * D + d] = f;               // row-major [j][e]
            }
            __syncthreads();
            {
                float s = 0.0f;
                #pragma unroll
                for (int ee = 0; ee < 4; ee++) {
                    int e = p * 4 + ee;
                    s += bk2T_g[e * D + d] * fyr[e];
                }
                part16[p][d] = s;
            }
            __syncthreads();
            if (p == 0) {
                float cc = 0.0f;
                #pragma unroll
                for (int r = 0; r < 16; r++) cc += part16[r][d];
                c_g[j * D + d] = cc;
            }
        }
        gsync(bar++);

        // ---- phase MG (block h): producer/consumer pipelined m3 -> G ----
        {
            int h = bid;
            float* m3c0 = sbuf + 8192;
            float* m3c1 = sbuf + 10240;
            #pragma unroll
            for (int r = 0; r < 4; r++)
                w2s[tid + r * 1024] = W2T_g[h * DD + tid + r * 1024];
            __syncthreads();

            const bool isProd = (tid < 512);
            int dq = tid & 15, jl = (tid >> 4) & 31;          // producer map
            int ct = tid & 511, cx = ct & 15, cy = ct >> 4;   // consumer map
            float ga[4][4] = {};
            float4 pre0 = make_float4(0.f,0.f,0.f,0.f), pre1 = pre0;

            for (int cb = 0; cb <= 4; cb++) {
                if (isProd) {
                    if (cb < 4) {                // produce m3 chunk cb -> buf cb&1
                        int j = cb * 32 + jl;
                        float m0 = 0.f, m1 = 0.f, m2 = 0.f, m3v = 0.f;
                        #pragma unroll
                        for (int e = 0; e < 64; e += 8) {
                            float4 fa = __ldcg((const float4*)&fy_g[j * D + e]);
                            float4 fb = __ldcg((const float4*)&fy_g[j * D + e + 4]);
                            float fv[8] = {fa.x, fa.y, fa.z, fa.w, fb.x, fb.y, fb.z, fb.w};
                            #pragma unroll
                            for (int ee = 0; ee < 8; ee++) {
                                float4 w4 = *(const float4*)&w2s[(e + ee) * 64 + dq * 4];
                                m0 += fv[ee] * w4.x; m1 += fv[ee] * w4.y;
                                m2 += fv[ee] * w4.z; m3v += fv[ee] * w4.w;
                            }
                        }
                        float* mb = (cb & 1) ? m3c1 : m3c0;
                        *(float4*)&mb[jl * 64 + dq * 4] = make_float4(m0, m1, m2, m3v);
                    }
                } else {
                    if (cb < 4) {                // prefetch a3 chunk cb to regs
                        const float4* ag = (const float4*)&A3_g[h * (T * T) + cb * 32 * T];
                        pre0 = ag[ct];
                        pre1 = ag[ct + 512];
                    }
                    if (cb > 0) {                // G for chunk cb-1 (a3c holds it)
                        int j0 = (cb - 1) * 32;
                        const float* mc = ((cb - 1) & 1) ? m3c1 : m3c0;
                        int jmax = cy * 4 + 4 - j0;
                        if (jmax > 32) jmax = 32;
                        for (int j = 0; j < jmax; j++) {
                            float4 a = *(const float4*)&a3c[j * 128 + cy * 4];
                            float4 b = *(const float4*)&mc[j * 64 + cx * 4];
                            ga[0][0] += a.x * b.x; ga[0][1] += a.x * b.y;
                            ga[0][2] += a.x * b.z; ga[0][3] += a.x * b.w;
                            ga[1][0] += a.y * b.x; ga[1][1] += a.y * b.y;
                            ga[1][2] += a.y * b.z; ga[1][3] += a.y * b.w;
                            ga[2][0] += a.z * b.x; ga[2][1] += a.z * b.y;
                            ga[2][2] += a.z * b.z; ga[2][3] += a.z * b.w;
                            ga[3][0] += a.w * b.x; ga[3][1] += a.w * b.y;
                            ga[3][2] += a.w * b.z; ga[3][3] += a.w * b.w;
                        }
                    }
                    if (cb < 4) {                // restage a3c (consumer-only barrier)
                        asm volatile("bar.sync 3, 512;" ::: "memory");
                        ((float4*)a3c)[ct] = pre0;
                        ((float4*)a3c)[ct + 512] = pre1;
                    }
                }
                __syncthreads();
            }
            if (!isProd) {
                float* gp = &Gpart_g[h * (T * D)];
                #pragma unroll
                for (int r = 0; r < 4; r++) {
                    float4 o = make_float4(ga[r][0], ga[r][1], ga[r][2], ga[r][3]);
                    *(float4*)&gp[(cy * 4 + r) * D + cx * 4] = o;
                }
            }
        }
        gsync(bar++);

        // ---- phase R (block i): reduce 128 h-slots + bias quadrature -> G ----
        {
            int i = bid;
            int d = tid & 63, p = tid >> 6;        // 16-way
            float s = 0.0f;
            #pragma unroll
            for (int sl = p; sl < NSLOT; sl += 16)
                s += __ldcg(&Gpart_g[sl * (T * D) + i * D + d]);
            for (int jj = p; jj <= i; jj += 16)
                s += wfun(i, jj, dt) * __ldcg(&c_g[jj * D + d]);
            part16[p][d] = s;
            __syncthreads();
            if (p == 0) {
                float acc = 0.0f;
                #pragma unroll
                for (int r = 0; r < 16; r++) acc += part16[r][d];
                G_g[i * D + d] = acc;
            }
        }
        gsync(bar++);
    }

    // ---- tail: block 127 computes out = y0 + (w@G)_{127} ----
    if (bid == T - 1) {
        int d = tid & 63, p = tid >> 6;
        float s = 0.0f;
        for (int i = p; i < T; i += 16)
            s += wfun(T - 1, i, dt) * __ldcg(&G_g[i * D + d]);
        part16[p][d] = s;
        __syncthreads();
        if (p == 0) {
            float acc = z0[d];
            #pragma unroll
            for (int r = 0; r < 16; r++) acc += part16[r][d];
            out[d] = acc;
        }
    }
}

extern "C" void kernel_launch(void* const* d_in, const int* in_sizes, int n_in,
                              void* d_out, int out_size) {
    const float* z0  = (const float*)d_in[0];
    const float* t   = (const float*)d_in[1];
    const float* W1  = (const float*)d_in[2];
    const float* b1  = (const float*)d_in[3];
    const float* W2  = (const float*)d_in[4];
    const float* b2  = (const float*)d_in[5];
    const float* Wk1 = (const float*)d_in[6];
    const float* bk1 = (const float*)d_in[7];
    const float* Wk2 = (const float*)d_in[8];
    const float* bk2 = (const float*)d_in[9];
    float* out = (float*)d_out;

    static int attr_done = 0;
    if (!attr_done) {
        cudaFuncSetAttribute(mega, cudaFuncAttributeMaxDynamicSharedMemorySize, 64 * 1024);
        attr_done = 1;
    }
    mega<<<NB, NT, 49152>>>(z0, t, W1, b1, W2, b2, Wk1, bk1, Wk2, bk2, out);
}

// round 12
// speedup vs baseline: 1.2421x; 1.1494x over previous
#include <cuda_runtime.h>
#include <math.h>

#define T    128
#define D    64
#define H    256
#define HK   128
#define DD   (D*D)
#define ITERS 3
#define NB   128
#define NT   1024
#define NSLOT 128
#define NBAR 16
#define NLEAF 16
#define SMEM_BYTES 147456   // 36864 floats: w2s 4096 | a3s 16384 | m3s 8192 | fys 8192

// ---- scratch (static device globals; no runtime allocation) ----
__device__ float A3_g[HK*T*T];         // 8 MB  A3[h][j][i] = w_ij * tanh(...)
__device__ float W2T_g[HK*DD];         // 2 MB  [h][e][d]
__device__ float bk2T_g[DD];           //       [e][d]
__device__ float fy_g[T*D];            //       f(y): [j][e]
__device__ float c_g[T*D];
__device__ float Gpart_g[NSLOT*T*D];   // 4 MB  slot = h
__device__ float G_g[T*D];

// hierarchical grid barrier (replay-safe: last root-departer resets all)
__device__ unsigned lfA[NBAR][NLEAF];
__device__ unsigned rtA[NBAR];
__device__ unsigned lfD[NBAR][NLEAF];
__device__ unsigned rtD[NBAR];

__device__ __forceinline__ void gsync(int b) {
    __syncthreads();
    if (threadIdx.x == 0) {
        __threadfence();
        int leaf = blockIdx.x & (NLEAF - 1);
        if (atomicAdd(&lfA[b][leaf], 1u) == 7u)
            atomicAdd(&rtA[b], 1u);
        while (*(volatile unsigned*)&rtA[b] < (unsigned)NLEAF) { }
        __threadfence();
        if (atomicAdd(&lfD[b][leaf], 1u) == 7u) {
            if (atomicAdd(&rtD[b], 1u) == (unsigned)(NLEAF - 1)) {
                #pragma unroll
                for (int l = 0; l < NLEAF; l++) { lfA[b][l] = 0u; lfD[b][l] = 0u; }
                rtA[b] = 0u;
                __threadfence();
                rtD[b] = 0u;
            }
        }
    }
    __syncthreads();
}

// trapezoid weight w[i][j]: w = dt*(j<=i); w[i,i]*=0.5; w[:,0]*=0.5; w[0,:]=0
__device__ __forceinline__ float wfun(int i, int j, float dt) {
    if (i == 0 || j > i) return 0.0f;
    float v = dt;
    if (j == i) v *= 0.5f;
    if (j == 0) v *= 0.5f;
    return v;
}

__global__ void __launch_bounds__(NT, 1) mega(
    const float* __restrict__ z0, const float* __restrict__ t,
    const float* __restrict__ W1, const float* __restrict__ b1,
    const float* __restrict__ W2, const float* __restrict__ b2,
    const float* __restrict__ Wk1, const float* __restrict__ bk1,
    const float* __restrict__ Wk2, const float* __restrict__ bk2,
    float* __restrict__ out)
{
    extern __shared__ float sbuf[];
    float* w2s = sbuf;              // [e][d]   4096
    float* a3s = sbuf + 4096;       // [j][i]  16384
    float* m3s = sbuf + 20480;      // [j][d]   8192
    float* fys = sbuf + 28672;      // [j][e]   8192
    __shared__ float ts[T];
    __shared__ float yrow[D], hid[H], fyr[D];
    __shared__ float part16[16][D];
    __shared__ float hidpart[4][H];

    int bid = blockIdx.x, tid = threadIdx.x;

    // ================= SETUP =================
    // W2T[h=bid][e][d] = Wk2[h][d*64+e] via padded smem transpose (scratch = a3s area)
    {
        float* tr = a3s;            // 67*64 = 4288 floats
        #pragma unroll
        for (int r = 0; r < 4; r++) {
            int idx = tid + r * 1024;
            tr[(idx >> 6) * 67 + (idx & 63)] = Wk2[bid * DD + idx];
        }
        __syncthreads();
        #pragma unroll
        for (int r = 0; r < 4; r++) {
            int idx = tid + r * 1024;
            W2T_g[bid * DD + idx] = tr[(idx & 63) * 67 + (idx >> 6)];
        }
        __syncthreads();
        if (bid == 0) {            // bk2T (block-uniform branch)
            #pragma unroll
            for (int r = 0; r < 4; r++) {
                int idx = tid + r * 1024;
                tr[(idx >> 6) * 67 + (idx & 63)] = bk2[idx];
            }
            __syncthreads();
            #pragma unroll
            for (int r = 0; r < 4; r++) {
                int idx = tid + r * 1024;
                bk2T_g[idx] = tr[(idx & 63) * 67 + (idx >> 6)];
            }
        }
    }
    if (tid < T) ts[tid] = t[tid];
    __syncthreads();
    float dt = ts[1] - ts[0];
    // A3[h=bid][j][i], coalesced over i
    {
        float wah = Wk1[bid], wbh = Wk1[HK + bid], bkh = bk1[bid];
        #pragma unroll 4
        for (int r = 0; r < 16; r++) {
            int idx = tid + r * 1024;              // j = idx>>7, i = idx&127
            int j = idx >> 7, i = idx & 127;
            float v = tanhf(ts[i] * wah + ts[j] * wbh + bkh);
            A3_g[bid * (T * T) + idx] = wfun(i, j, dt) * v;
        }
    }

    int bar = 0;
    gsync(bar++);

    // ================= FIXED-POINT ITERATIONS =================
    for (int it = 0; it < ITERS; it++) {
        // ---- phase F (block j): y_j = y0 + (w@G)_j (fused), then fy[j], c[j] ----
        {
            int j = bid;
            int d = tid & 63, p = tid >> 6;        // 16-way split
            if (it == 0) {
                if (tid < D) yrow[tid] = z0[tid];
            } else {
                float s = 0.0f;
                #pragma unroll
                for (int r = 0; r < 8; r++) {      // fixed trip; wfun zeroes i>j
                    int i = p + r * 16;
                    s += wfun(j, i, dt) * __ldcg(&G_g[i * D + d]);
                }
                part16[p][d] = s;
                __syncthreads();
                if (p == 0) {
                    float acc = z0[d];
                    #pragma unroll
                    for (int r = 0; r < 16; r++) acc += part16[r][d];
                    yrow[d] = acc;
                }
            }
            __syncthreads();
            {
                int h = tid & 255, q = tid >> 8;
                float s = (q == 0) ? b1[h] : 0.0f;
                #pragma unroll
                for (int ee = 0; ee < 16; ee++) {
                    int e = q * 16 + ee;
                    s += yrow[e] * W1[e * H + h];
                }
                hidpart[q][h] = s;
            }
            __syncthreads();
            if (tid < H)
                hid[tid] = tanhf(hidpart[0][tid] + hidpart[1][tid] + hidpart[2][tid] + hidpart[3][tid]);
            __syncthreads();
            {
                float s = 0.0f;
                #pragma unroll
                for (int hh = 0; hh < 16; hh++) {
                    int h = p * 16 + hh;
                    s += hid[h] * W2[h * D + d];
                }
                part16[p][d] = s;
            }
            __syncthreads();
            if (p == 0) {
                float f = b2[d];
                #pragma unroll
                for (int r = 0; r < 16; r++) f += part16[r][d];
                fyr[d] = f;
                fy_g[j * D + d] = f;               // row-major [j][e]
            }
            __syncthreads();
            {
                float s = 0.0f;
                #pragma unroll
                for (int ee = 0; ee < 4; ee++) {
                    int e = p * 4 + ee;
                    s += bk2T_g[e * D + d] * fyr[e];
                }
                part16[p][d] = s;
            }
            __syncthreads();
            if (p == 0) {
                float cc = 0.0f;
                #pragma unroll
                for (int r = 0; r < 16; r++) cc += part16[r][d];
                c_g[j * D + d] = cc;
            }
        }
        gsync(bar++);

        // ---- phase MG (block h): full tiles in smem, m3 then G, 2 syncs ----
        {
            int h = bid;
            // stage: w2s (16 KB), a3s (64 KB), fys (32 KB)
            #pragma unroll
            for (int r = 0; r < 4; r++)
                w2s[tid + r * 1024] = W2T_g[h * DD + tid + r * 1024];
            {
                const float4* ag = (const float4*)&A3_g[h * (T * T)];
                float4* a4 = (float4*)a3s;
                #pragma unroll
                for (int r = 0; r < 4; r++)
                    a4[tid + r * 1024] = __ldcg(ag + tid + r * 1024);
                const float4* fg = (const float4*)fy_g;
                float4* f4 = (float4*)fys;
                #pragma unroll
                for (int r = 0; r < 2; r++)
                    f4[tid + r * 1024] = __ldcg(fg + tid + r * 1024);
            }
            __syncthreads();
            // m3[j][d] = sum_e fys[j][e] * w2s[e][d]; thread (dq, jq): j in {jq, jq+64}
            {
                int dq = tid & 15, jq = tid >> 4;
                float a0=0,a1=0,a2=0,a3v=0, b0=0,b1=0,b2=0,b3=0;
                #pragma unroll 16
                for (int e = 0; e < 64; e++) {
                    float4 w4 = *(const float4*)&w2s[e * 64 + dq * 4];
                    float f0 = fys[jq * 64 + e];
                    float f1 = fys[(jq + 64) * 64 + e];
                    a0 += f0 * w4.x; a1 += f0 * w4.y; a2 += f0 * w4.z; a3v += f0 * w4.w;
                    b0 += f1 * w4.x; b1 += f1 * w4.y; b2 += f1 * w4.z; b3  += f1 * w4.w;
                }
                *(float4*)&m3s[jq * 64 + dq * 4]        = make_float4(a0, a1, a2, a3v);
                *(float4*)&m3s[(jq + 64) * 64 + dq * 4] = make_float4(b0, b1, b2, b3);
            }
            __syncthreads();
            // G[i][d] = sum_j a3s[j][i] * m3s[j][d]; thread (cx, cy): rows i2=cy*2
            {
                int cx = tid & 15, cy = tid >> 4;
                int i2 = cy * 2;
                float g00=0,g01=0,g02=0,g03=0,g10=0,g11=0,g12=0,g13=0;
                for (int jb = 0; jb < 8; jb++) {
                    if (jb * 16 <= i2 + 1) {       // chunk-level triangular skip
                        #pragma unroll
                        for (int jj = 0; jj < 16; jj++) {
                            int j = jb * 16 + jj;
                            float2 a = *(const float2*)&a3s[j * 128 + i2];
                            float4 b = *(const float4*)&m3s[j * 64 + cx * 4];
                            g00 += a.x * b.x; g01 += a.x * b.y;
                            g02 += a.x * b.z; g03 += a.x * b.w;
                            g10 += a.y * b.x; g11 += a.y * b.y;
                            g12 += a.y * b.z; g13 += a.y * b.w;
                        }
                    }
                }
                float* gp = &Gpart_g[h * (T * D)];
                *(float4*)&gp[i2 * D + cx * 4]       = make_float4(g00, g01, g02, g03);
                *(float4*)&gp[(i2 + 1) * D + cx * 4] = make_float4(g10, g11, g12, g13);
            }
        }
        gsync(bar++);

        // ---- phase R (block i): reduce 128 h-slots + bias quadrature -> G ----
        {
            int i = bid;
            int d = tid & 63, p = tid >> 6;        // 16-way
            float s = 0.0f;
            #pragma unroll
            for (int sl = p; sl < NSLOT; sl += 16)
                s += __ldcg(&Gpart_g[sl * (T * D) + i * D + d]);
            #pragma unroll
            for (int r = 0; r < 8; r++) {          // fixed trip; wfun zeroes jj>i
                int jj = p + r * 16;
                s += wfun(i, jj, dt) * __ldcg(&c_g[jj * D + d]);
            }
            part16[p][d] = s;
            __syncthreads();
            if (p == 0) {
                float acc = 0.0f;
                #pragma unroll
                for (int r = 0; r < 16; r++) acc += part16[r][d];
                G_g[i * D + d] = acc;
            }
        }
        gsync(bar++);
    }

    // ---- tail: block 127 computes out = y0 + (w@G)_{127} ----
    if (bid == T - 1) {
        int d = tid & 63, p = tid >> 6;
        float s = 0.0f;
        #pragma unroll
        for (int r = 0; r < 8; r++) {
            int i = p + r * 16;
            s += wfun(T - 1, i, dt) * __ldcg(&G_g[i * D + d]);
        }
        part16[p][d] = s;
        __syncthreads();
        if (p == 0) {
            float acc = z0[d];
            #pragma unroll
            for (int r = 0; r < 16; r++) acc += part16[r][d];
            out[d] = acc;
        }
    }
}

extern "C" void kernel_launch(void* const* d_in, const int* in_sizes, int n_in,
                              void* d_out, int out_size) {
    const float* z0  = (const float*)d_in[0];
    const float* t   = (const float*)d_in[1];
    const float* W1  = (const float*)d_in[2];
    const float* b1  = (const float*)d_in[3];
    const float* W2  = (const float*)d_in[4];
    const float* b2  = (const float*)d_in[5];
    const float* Wk1 = (const float*)d_in[6];
    const float* bk1 = (const float*)d_in[7];
    const float* Wk2 = (const float*)d_in[8];
    const float* bk2 = (const float*)d_in[9];
    float* out = (float*)d_out;

    static int attr_done = 0;
    if (!attr_done) {
        cudaFuncSetAttribute(mega, cudaFuncAttributeMaxDynamicSharedMemorySize, SMEM_BYTES);
        attr_done = 1;
    }
    mega<<<NB, NT, SMEM_BYTES>>>(z0, t, W1, b1, W2, b2, Wk1, bk1, Wk2, bk2, out);
}

// round 13
// speedup vs baseline: 1.4486x; 1.1662x over previous
#include <cuda_runtime.h>
#include <math.h>

#define T    128
#define D    64
#define H    256
#define HK   128
#define DD   (D*D)
#define ITERS 3
#define NB   128
#define NT   512
#define NSLOT 128
#define NBAR 16
#define NLEAF 16
#define SMEM_BYTES 147456   // 36864 floats: w2s 4096 | a3s 16384 | m3s 8192 | fys 8192

// ---- scratch (static device globals; no runtime allocation) ----
__device__ float A3_g[HK*T*T];         // 8 MB  A3[h][j][i] = w_ij * tanh(...)
__device__ float W2T_g[HK*DD];         // 2 MB  [h][e][d]
__device__ float bk2T_g[DD];           //       [e][d]
__device__ float fy_g[T*D];            //       f(y): [j][e]
__device__ float c_g[T*D];
__device__ float Gpart_g[NSLOT*T*D];   // 4 MB  slot = h
__device__ float G_g[T*D];

// hierarchical grid barrier (replay-safe: last root-departer resets all)
__device__ unsigned lfA[NBAR][NLEAF];
__device__ unsigned rtA[NBAR];
__device__ unsigned lfD[NBAR][NLEAF];
__device__ unsigned rtD[NBAR];

__device__ __forceinline__ void gsync(int b) {
    __syncthreads();
    if (threadIdx.x == 0) {
        __threadfence();
        int leaf = blockIdx.x & (NLEAF - 1);
        if (atomicAdd(&lfA[b][leaf], 1u) == 7u)
            atomicAdd(&rtA[b], 1u);
        while (*(volatile unsigned*)&rtA[b] < (unsigned)NLEAF) { }
        __threadfence();
        if (atomicAdd(&lfD[b][leaf], 1u) == 7u) {
            if (atomicAdd(&rtD[b], 1u) == (unsigned)(NLEAF - 1)) {
                #pragma unroll
                for (int l = 0; l < NLEAF; l++) { lfA[b][l] = 0u; lfD[b][l] = 0u; }
                rtA[b] = 0u;
                __threadfence();
                rtD[b] = 0u;
            }
        }
    }
    __syncthreads();
}

__device__ __forceinline__ void cpa16(float* s, const float* g) {
    unsigned sa = (unsigned)__cvta_generic_to_shared(s);
    asm volatile("cp.async.cg.shared.global [%0], [%1], 16;" :: "r"(sa), "l"(g));
}

// trapezoid weight w[i][j]: w = dt*(j<=i); w[i,i]*=0.5; w[:,0]*=0.5; w[0,:]=0
__device__ __forceinline__ float wfun(int i, int j, float dt) {
    if (i == 0 || j > i) return 0.0f;
    float v = dt;
    if (j == i) v *= 0.5f;
    if (j == 0) v *= 0.5f;
    return v;
}

__global__ void __launch_bounds__(NT, 1) mega(
    const float* __restrict__ z0, const float* __restrict__ t,
    const float* __restrict__ W1, const float* __restrict__ b1,
    const float* __restrict__ W2, const float* __restrict__ b2,
    const float* __restrict__ Wk1, const float* __restrict__ bk1,
    const float* __restrict__ Wk2, const float* __restrict__ bk2,
    float* __restrict__ out)
{
    extern __shared__ float sbuf[];
    float* w2s = sbuf;              // [e][d]   4096
    float* a3s = sbuf + 4096;       // [j][i]  16384
    float* m3s = sbuf + 20480;      // [j][d]   8192
    float* fys = sbuf + 28672;      // [j][e]   8192
    __shared__ float ts[T];
    __shared__ float yrow[D], hid[H], fyr[D];
    __shared__ float part8[8][D];
    __shared__ float hidpart[2][H];

    int bid = blockIdx.x, tid = threadIdx.x;

    // ================= SETUP =================
    // W2T[h=bid][e][d] = Wk2[h][d*64+e] via padded smem transpose (scratch = a3s area)
    {
        float* tr = a3s;            // 67*64 = 4288 floats
        #pragma unroll
        for (int r = 0; r < 8; r++) {
            int idx = tid + r * 512;
            tr[(idx >> 6) * 67 + (idx & 63)] = Wk2[bid * DD + idx];
        }
        __syncthreads();
        #pragma unroll
        for (int r = 0; r < 8; r++) {
            int idx = tid + r * 512;
            W2T_g[bid * DD + idx] = tr[(idx & 63) * 67 + (idx >> 6)];
        }
        __syncthreads();
        if (bid == 0) {            // bk2T (block-uniform branch)
            #pragma unroll
            for (int r = 0; r < 8; r++) {
                int idx = tid + r * 512;
                tr[(idx >> 6) * 67 + (idx & 63)] = bk2[idx];
            }
            __syncthreads();
            #pragma unroll
            for (int r = 0; r < 8; r++) {
                int idx = tid + r * 512;
                bk2T_g[idx] = tr[(idx & 63) * 67 + (idx >> 6)];
            }
        }
    }
    if (tid < T) ts[tid] = t[tid];
    __syncthreads();
    float dt = ts[1] - ts[0];
    // A3[h=bid][j][i], coalesced over i
    {
        float wah = Wk1[bid], wbh = Wk1[HK + bid], bkh = bk1[bid];
        #pragma unroll 4
        for (int r = 0; r < 32; r++) {
            int idx = tid + r * 512;               // j = idx>>7, i = idx&127
            int j = idx >> 7, i = idx & 127;
            float v = tanhf(ts[i] * wah + ts[j] * wbh + bkh);
            A3_g[bid * (T * T) + idx] = wfun(i, j, dt) * v;
        }
    }

    int bar = 0;
    gsync(bar++);

    // ================= FIXED-POINT ITERATIONS =================
    for (int it = 0; it < ITERS; it++) {
        // prefetch MG's iteration-invariant operands under the F phase
        {
            const float4* wg = (const float4*)&W2T_g[bid * DD];
            #pragma unroll
            for (int r = 0; r < 2; r++)
                cpa16(&w2s[(tid + r * 512) * 4], (const float*)(wg + tid + r * 512));
            const float4* ag = (const float4*)&A3_g[bid * (T * T)];
            #pragma unroll
            for (int r = 0; r < 8; r++)
                cpa16(&a3s[(tid + r * 512) * 4], (const float*)(ag + tid + r * 512));
            asm volatile("cp.async.commit_group;" ::: "memory");
        }

        // ---- phase F (block j): y_j = y0 + (w@G)_j (fused), then fy[j], c[j] ----
        {
            int j = bid;
            int d = tid & 63, p = tid >> 6;        // 8-way split
            if (it == 0) {
                if (tid < D) yrow[tid] = z0[tid];
            } else {
                float s = 0.0f;
                #pragma unroll
                for (int r = 0; r < 16; r++) {     // fixed trip; wfun zeroes i>j
                    int i = p + r * 8;
                    s += wfun(j, i, dt) * __ldcg(&G_g[i * D + d]);
                }
                part8[p][d] = s;
                __syncthreads();
                if (p == 0) {
                    float acc = z0[d];
                    #pragma unroll
                    for (int r = 0; r < 8; r++) acc += part8[r][d];
                    yrow[d] = acc;
                }
            }
            __syncthreads();
            {
                int h = tid & 255, q = tid >> 8;   // 2-way split over e
                float s = (q == 0) ? b1[h] : 0.0f;
                #pragma unroll
                for (int ee = 0; ee < 32; ee++) {
                    int e = q * 32 + ee;
                    s += yrow[e] * W1[e * H + h];
                }
                hidpart[q][h] = s;
            }
            __syncthreads();
            if (tid < H)
                hid[tid] = tanhf(hidpart[0][tid] + hidpart[1][tid]);
            __syncthreads();
            {
                float s = 0.0f;
                #pragma unroll
                for (int hh = 0; hh < 32; hh++) {
                    int h = p * 32 + hh;
                    s += hid[h] * W2[h * D + d];
                }
                part8[p][d] = s;
            }
            __syncthreads();
            if (p == 0) {
                float f = b2[d];
                #pragma unroll
                for (int r = 0; r < 8; r++) f += part8[r][d];
                fyr[d] = f;
                fy_g[j * D + d] = f;               // row-major [j][e]
            }
            __syncthreads();
            {
                float s = 0.0f;
                #pragma unroll
                for (int ee = 0; ee < 8; ee++) {
                    int e = p * 8 + ee;
                    s += bk2T_g[e * D + d] * fyr[e];
                }
                part8[p][d] = s;
            }
            __syncthreads();
            if (p == 0) {
                float cc = 0.0f;
                #pragma unroll
                for (int r = 0; r < 8; r++) cc += part8[r][d];
                c_g[j * D + d] = cc;
            }
        }
        gsync(bar++);

        // ---- phase MG (block h): full smem tiles, m3 then G ----
        {
            int h = bid;
            // fys staged now (depends on F of this iter); a3/w2 arrive via cp.async
            {
                const float4* fg = (const float4*)fy_g;
                float4* f4 = (float4*)fys;
                #pragma unroll
                for (int r = 0; r < 4; r++)
                    f4[tid + r * 512] = __ldcg(fg + tid + r * 512);
            }
            asm volatile("cp.async.wait_group 0;" ::: "memory");
            __syncthreads();
            // m3[j][d] = sum_e fys[j][e] * w2s[e][d]; thread: 4j x 4d
            {
                int dq = tid & 15, jt = tid >> 4;          // d = dq*4, j = jt*4+r
                float acc[4][4] = {};
                #pragma unroll 8
                for (int e = 0; e < 64; e++) {
                    float4 w4 = *(const float4*)&w2s[e * 64 + dq * 4];
                    #pragma unroll
                    for (int r = 0; r < 4; r++) {
                        float f = fys[(jt * 4 + r) * 64 + e];
                        acc[r][0] += f * w4.x; acc[r][1] += f * w4.y;
                        acc[r][2] += f * w4.z; acc[r][3] += f * w4.w;
                    }
                }
                #pragma unroll
                for (int r = 0; r < 4; r++)
                    *(float4*)&m3s[(jt * 4 + r) * 64 + dq * 4] =
                        make_float4(acc[r][0], acc[r][1], acc[r][2], acc[r][3]);
            }
            __syncthreads();
            // G[i][d] = sum_j a3s[j][i] * m3s[j][d]; thread: 4i x 4d
            {
                int cx = tid & 15, cy = tid >> 4;          // d = cx*4, i = cy*4+r
                int i0 = cy * 4;
                float g[4][4] = {};
                for (int jb = 0; jb < 8; jb++) {
                    if (jb * 16 <= i0 + 3) {   // chunk-level triangular skip
                        #pragma unroll
                        for (int jj = 0; jj < 16; jj++) {
                            int j = jb * 16 + jj;
                            float4 a = *(const float4*)&a3s[j * 128 + i0];
                            float4 b = *(const float4*)&m3s[j * 64 + cx * 4];
                            g[0][0] += a.x * b.x; g[0][1] += a.x * b.y;
                            g[0][2] += a.x * b.z; g[0][3] += a.x * b.w;
                            g[1][0] += a.y * b.x; g[1][1] += a.y * b.y;
                            g[1][2] += a.y * b.z; g[1][3] += a.y * b.w;
                            g[2][0] += a.z * b.x; g[2][1] += a.z * b.y;
                            g[2][2] += a.z * b.z; g[2][3] += a.z * b.w;
                            g[3][0] += a.w * b.x; g[3][1] += a.w * b.y;
                            g[3][2] += a.w * b.z; g[3][3] += a.w * b.w;
                        }
                    }
                }
                float* gp = &Gpart_g[h * (T * D)];
                #pragma unroll
                for (int r = 0; r < 4; r++)
                    *(float4*)&gp[(i0 + r) * D + cx * 4] =
                        make_float4(g[r][0], g[r][1], g[r][2], g[r][3]);
            }
        }
        gsync(bar++);

        // ---- phase R (block i): reduce 128 h-slots + bias quadrature -> G ----
        {
            int i = bid;
            int d = tid & 63, p = tid >> 6;        // 8-way
            float s = 0.0f;
            #pragma unroll
            for (int sl = p; sl < NSLOT; sl += 8)
                s += __ldcg(&Gpart_g[sl * (T * D) + i * D + d]);
            #pragma unroll
            for (int r = 0; r < 16; r++) {         // fixed trip; wfun zeroes jj>i
                int jj = p + r * 8;
                s += wfun(i, jj, dt) * __ldcg(&c_g[jj * D + d]);
            }
            part8[p][d] = s;
            __syncthreads();
            if (p == 0) {
                float acc = 0.0f;
                #pragma unroll
                for (int r = 0; r < 8; r++) acc += part8[r][d];
                G_g[i * D + d] = acc;
            }
        }
        gsync(bar++);
    }

    // ---- tail: block 127 computes out = y0 + (w@G)_{127} ----
    if (bid == T - 1) {
        int d = tid & 63, p = tid >> 6;
        float s = 0.0f;
        #pragma unroll
        for (int r = 0; r < 16; r++) {
            int i = p + r * 8;
            s += wfun(T - 1, i, dt) * __ldcg(&G_g[i * D + d]);
        }
        part8[p][d] = s;
        __syncthreads();
        if (p == 0) {
            float acc = z0[d];
            #pragma unroll
            for (int r = 0; r < 8; r++) acc += part8[r][d];
            out[d] = acc;
        }
    }
}

extern "C" void kernel_launch(void* const* d_in, const int* in_sizes, int n_in,
                              void* d_out, int out_size) {
    const float* z0  = (const float*)d_in[0];
    const float* t   = (const float*)d_in[1];
    const float* W1  = (const float*)d_in[2];
    const float* b1  = (const float*)d_in[3];
    const float* W2  = (const float*)d_in[4];
    const float* b2  = (const float*)d_in[5];
    const float* Wk1 = (const float*)d_in[6];
    const float* bk1 = (const float*)d_in[7];
    const float* Wk2 = (const float*)d_in[8];
    const float* bk2 = (const float*)d_in[9];
    float* out = (float*)d_out;

    static int attr_done = 0;
    if (!attr_done) {
        cudaFuncSetAttribute(mega, cudaFuncAttributeMaxDynamicSharedMemorySize, SMEM_BYTES);
        attr_done = 1;
    }
    mega<<<NB, NT, SMEM_BYTES>>>(z0, t, W1, b1, W2, b2, Wk1, bk1, Wk2, bk2, out);
}

// round 14
// speedup vs baseline: 1.4821x; 1.0231x over previous
#include <cuda_runtime.h>
#include <math.h>

#define T    128
#define D    64
#define H    256
#define HK   128
#define DD   (D*D)
#define ITERS 3
#define NB   128
#define NT   512
#define NSLOT 128
#define NBAR 16
#define NLEAF 16
#define SMEM_BYTES 147456   // 36864 floats: w2s 4096 | a3s 16384 | m3s 8192 | fys 8192

// ---- scratch (static device globals; no runtime allocation) ----
__device__ float A3_g[HK*T*T];         // 8 MB  A3[h][j][i] = w_ij * tanh(...)
__device__ float W2T_g[HK*DD];         // 2 MB  [h][e][d]
__device__ float bk2T_g[DD];           //       [e][d]
__device__ float fy_g[T*D];            //       f(y): [j][e]
__device__ float c_g[T*D];
__device__ float Gpart_g[NSLOT*T*D];   // 4 MB  slot = h
__device__ float G_g[T*D];

// hierarchical grid barrier (replay-safe: last root-departer resets all)
__device__ unsigned lfA[NBAR][NLEAF];
__device__ unsigned rtA[NBAR];
__device__ unsigned lfD[NBAR][NLEAF];
__device__ unsigned rtD[NBAR];

__device__ __forceinline__ void gsync(int b) {
    __syncthreads();
    if (threadIdx.x == 0) {
        __threadfence();
        int leaf = blockIdx.x & (NLEAF - 1);
        if (atomicAdd(&lfA[b][leaf], 1u) == 7u)
            atomicAdd(&rtA[b], 1u);
        while (*(volatile unsigned*)&rtA[b] < (unsigned)NLEAF) { }
        __threadfence();
        if (atomicAdd(&lfD[b][leaf], 1u) == 7u) {
            if (atomicAdd(&rtD[b], 1u) == (unsigned)(NLEAF - 1)) {
                #pragma unroll
                for (int l = 0; l < NLEAF; l++) { lfA[b][l] = 0u; lfD[b][l] = 0u; }
                rtA[b] = 0u;
                __threadfence();
                rtD[b] = 0u;
            }
        }
    }
    __syncthreads();
}

__device__ __forceinline__ void cpa16(float* s, const float* g) {
    unsigned sa = (unsigned)__cvta_generic_to_shared(s);
    asm volatile("cp.async.cg.shared.global [%0], [%1], 16;" :: "r"(sa), "l"(g));
}

// packed fp32x2 helpers (FFMA2 — only reachable via explicit PTX)
__device__ __forceinline__ unsigned long long splat2(float x) {
    unsigned long long r;
    unsigned int u = __float_as_uint(x);
    asm("mov.b64 %0, {%1, %1};" : "=l"(r) : "r"(u));
    return r;
}
__device__ __forceinline__ void ffma2(unsigned long long& d,
                                      unsigned long long a, unsigned long long b) {
    asm("fma.rn.f32x2 %0, %1, %2, %3;" : "=l"(d) : "l"(a), "l"(b), "l"(d));
}

// trapezoid weight w[i][j]: w = dt*(j<=i); w[i,i]*=0.5; w[:,0]*=0.5; w[0,:]=0
__device__ __forceinline__ float wfun(int i, int j, float dt) {
    if (i == 0 || j > i) return 0.0f;
    float v = dt;
    if (j == i) v *= 0.5f;
    if (j == 0) v *= 0.5f;
    return v;
}

__global__ void __launch_bounds__(NT, 1) mega(
    const float* __restrict__ z0, const float* __restrict__ t,
    const float* __restrict__ W1, const float* __restrict__ b1,
    const float* __restrict__ W2, const float* __restrict__ b2,
    const float* __restrict__ Wk1, const float* __restrict__ bk1,
    const float* __restrict__ Wk2, const float* __restrict__ bk2,
    float* __restrict__ out)
{
    extern __shared__ float sbuf[];
    float* w2s = sbuf;              // [e][d]   4096
    float* a3s = sbuf + 4096;       // [j][i]  16384
    float* m3s = sbuf + 20480;      // [j][d]   8192
    float* fys = sbuf + 28672;      // [j][e]   8192
    __shared__ float ts[T];
    __shared__ float yrow[D], hid[H], fyr[D];
    __shared__ float part8[8][D];
    __shared__ float hidpart[2][H];

    int bid = blockIdx.x, tid = threadIdx.x;

    // ================= SETUP =================
    {
        float* tr = a3s;            // 67*64 = 4288 floats
        #pragma unroll
        for (int r = 0; r < 8; r++) {
            int idx = tid + r * 512;
            tr[(idx >> 6) * 67 + (idx & 63)] = Wk2[bid * DD + idx];
        }
        __syncthreads();
        #pragma unroll
        for (int r = 0; r < 8; r++) {
            int idx = tid + r * 512;
            W2T_g[bid * DD + idx] = tr[(idx & 63) * 67 + (idx >> 6)];
        }
        __syncthreads();
        if (bid == 0) {            // bk2T (block-uniform branch)
            #pragma unroll
            for (int r = 0; r < 8; r++) {
                int idx = tid + r * 512;
                tr[(idx >> 6) * 67 + (idx & 63)] = bk2[idx];
            }
            __syncthreads();
            #pragma unroll
            for (int r = 0; r < 8; r++) {
                int idx = tid + r * 512;
                bk2T_g[idx] = tr[(idx & 63) * 67 + (idx >> 6)];
            }
        }
    }
    if (tid < T) ts[tid] = t[tid];
    __syncthreads();
    float dt = ts[1] - ts[0];
    // A3[h=bid][j][i], coalesced over i
    {
        float wah = Wk1[bid], wbh = Wk1[HK + bid], bkh = bk1[bid];
        #pragma unroll 4
        for (int r = 0; r < 32; r++) {
            int idx = tid + r * 512;               // j = idx>>7, i = idx&127
            int j = idx >> 7, i = idx & 127;
            float v = tanhf(ts[i] * wah + ts[j] * wbh + bkh);
            A3_g[bid * (T * T) + idx] = wfun(i, j, dt) * v;
        }
    }

    int bar = 0;
    gsync(bar++);

    // ================= FIXED-POINT ITERATIONS =================
    for (int it = 0; it < ITERS; it++) {
        // prefetch MG's iteration-invariant operands under the F phase
        {
            const float4* wg = (const float4*)&W2T_g[bid * DD];
            #pragma unroll
            for (int r = 0; r < 2; r++)
                cpa16(&w2s[(tid + r * 512) * 4], (const float*)(wg + tid + r * 512));
            const float4* ag = (const float4*)&A3_g[bid * (T * T)];
            #pragma unroll
            for (int r = 0; r < 8; r++)
                cpa16(&a3s[(tid + r * 512) * 4], (const float*)(ag + tid + r * 512));
            asm volatile("cp.async.commit_group;" ::: "memory");
        }

        // ---- phase F (block j): y_j = y0 + (w@G)_j (fused), then fy[j], c[j] ----
        {
            int j = bid;
            int d = tid & 63, p = tid >> 6;        // 8-way split
            if (it == 0) {
                if (tid < D) yrow[tid] = z0[tid];
            } else {
                float s = 0.0f;
                #pragma unroll
                for (int r = 0; r < 16; r++) {     // fixed trip; wfun zeroes i>j
                    int i = p + r * 8;
                    s += wfun(j, i, dt) * __ldcg(&G_g[i * D + d]);
                }
                part8[p][d] = s;
                __syncthreads();
                if (p == 0) {
                    float acc = z0[d];
                    #pragma unroll
                    for (int r = 0; r < 8; r++) acc += part8[r][d];
                    yrow[d] = acc;
                }
            }
            __syncthreads();
            {
                int h = tid & 255, q = tid >> 8;   // 2-way split over e
                float s = (q == 0) ? b1[h] : 0.0f;
                #pragma unroll
                for (int ee = 0; ee < 32; ee++) {
                    int e = q * 32 + ee;
                    s += yrow[e] * W1[e * H + h];
                }
                hidpart[q][h] = s;
            }
            __syncthreads();
            if (tid < H)
                hid[tid] = tanhf(hidpart[0][tid] + hidpart[1][tid]);
            __syncthreads();
            {
                float s = 0.0f;
                #pragma unroll
                for (int hh = 0; hh < 32; hh++) {
                    int h = p * 32 + hh;
                    s += hid[h] * W2[h * D + d];
                }
                part8[p][d] = s;
            }
            __syncthreads();
            if (p == 0) {
                float f = b2[d];
                #pragma unroll
                for (int r = 0; r < 8; r++) f += part8[r][d];
                fyr[d] = f;
                fy_g[j * D + d] = f;               // row-major [j][e]
            }
            __syncthreads();
            {
                float s = 0.0f;
                #pragma unroll
                for (int ee = 0; ee < 8; ee++) {
                    int e = p * 8 + ee;
                    s += bk2T_g[e * D + d] * fyr[e];
                }
                part8[p][d] = s;
            }
            __syncthreads();
            if (p == 0) {
                float cc = 0.0f;
                #pragma unroll
                for (int r = 0; r < 8; r++) cc += part8[r][d];
                c_g[j * D + d] = cc;
            }
        }
        gsync(bar++);

        // ---- phase MG (block h): full smem tiles, f32x2-packed m3 then G ----
        {
            int h = bid;
            {
                const float4* fg = (const float4*)fy_g;
                float4* f4 = (float4*)fys;
                #pragma unroll
                for (int r = 0; r < 4; r++)
                    f4[tid + r * 512] = __ldcg(fg + tid + r * 512);
            }
            asm volatile("cp.async.wait_group 0;" ::: "memory");
            __syncthreads();
            // m3[j][d] = sum_e fys[j][e] * w2s[e][d]; thread: 4j x (2 d-pairs)
            {
                int dq = tid & 15, jt = tid >> 4;          // d = dq*4, j = jt*4+r
                unsigned long long acc[4][2] = {};
                #pragma unroll
                for (int e4 = 0; e4 < 16; e4++) {
                    float4 fv[4];
                    #pragma unroll
                    for (int r = 0; r < 4; r++)
                        fv[r] = *(const float4*)&fys[(jt * 4 + r) * 64 + e4 * 4];
                    #pragma unroll
                    for (int ee = 0; ee < 4; ee++) {
                        int e = e4 * 4 + ee;
                        ulonglong2 w2 = *(const ulonglong2*)&w2s[e * 64 + dq * 4];
                        #pragma unroll
                        for (int r = 0; r < 4; r++) {
                            float f = (ee == 0) ? fv[r].x : (ee == 1) ? fv[r].y
                                    : (ee == 2) ? fv[r].z : fv[r].w;
                            unsigned long long fs = splat2(f);
                            ffma2(acc[r][0], fs, w2.x);
                            ffma2(acc[r][1], fs, w2.y);
                        }
                    }
                }
                #pragma unroll
                for (int r = 0; r < 4; r++)
                    *(ulonglong2*)&m3s[(jt * 4 + r) * 64 + dq * 4] =
                        make_ulonglong2(acc[r][0], acc[r][1]);
            }
            __syncthreads();
            // G[i][d] = sum_j a3s[j][i] * m3s[j][d]; thread: (2 i-pairs) x 4 d
            {
                int cx = tid & 15, cy = tid >> 4;          // d = cx*4, i = cy*4
                int i0 = cy * 4;
                unsigned long long g2[2][4] = {};
                for (int jb = 0; jb < 8; jb++) {
                    if (jb * 16 <= i0 + 3) {   // chunk-level triangular skip
                        #pragma unroll
                        for (int jj = 0; jj < 16; jj++) {
                            int j = jb * 16 + jj;
                            ulonglong2 ap = *(const ulonglong2*)&a3s[j * 128 + i0];
                            float4 b = *(const float4*)&m3s[j * 64 + cx * 4];
                            unsigned long long bs0 = splat2(b.x), bs1 = splat2(b.y),
                                               bs2 = splat2(b.z), bs3 = splat2(b.w);
                            ffma2(g2[0][0], ap.x, bs0); ffma2(g2[0][1], ap.x, bs1);
                            ffma2(g2[0][2], ap.x, bs2); ffma2(g2[0][3], ap.x, bs3);
                            ffma2(g2[1][0], ap.y, bs0); ffma2(g2[1][1], ap.y, bs1);
                            ffma2(g2[1][2], ap.y, bs2); ffma2(g2[1][3], ap.y, bs3);
                        }
                    }
                }
                // unpack: g2[ip][c] = {G[i0+2ip][c], G[i0+2ip+1][c]}
                float* gp = &Gpart_g[h * (T * D)];
                #pragma unroll
                for (int ip = 0; ip < 2; ip++) {
                    float lo[4], hi[4];
                    #pragma unroll
                    for (int c = 0; c < 4; c++) {
                        unsigned int l, hb;
                        asm("mov.b64 {%0, %1}, %2;" : "=r"(l), "=r"(hb) : "l"(g2[ip][c]));
                        lo[c] = __uint_as_float(l);
                        hi[c] = __uint_as_float(hb);
                    }
                    *(float4*)&gp[(i0 + 2 * ip) * D + cx * 4] =
                        make_float4(lo[0], lo[1], lo[2], lo[3]);
                    *(float4*)&gp[(i0 + 2 * ip + 1) * D + cx * 4] =
                        make_float4(hi[0], hi[1], hi[2], hi[3]);
                }
            }
        }
        gsync(bar++);

        // ---- phase R (block i): reduce 128 h-slots + bias quadrature -> G ----
        {
            int i = bid;
            int d = tid & 63, p = tid >> 6;        // 8-way
            float s = 0.0f;
            #pragma unroll
            for (int sl = p; sl < NSLOT; sl += 8)
                s += __ldcg(&Gpart_g[sl * (T * D) + i * D + d]);
            #pragma unroll
            for (int r = 0; r < 16; r++) {         // fixed trip; wfun zeroes jj>i
                int jj = p + r * 8;
                s += wfun(i, jj, dt) * __ldcg(&c_g[jj * D + d]);
            }
            part8[p][d] = s;
            __syncthreads();
            if (p == 0) {
                float acc = 0.0f;
                #pragma unroll
                for (int r = 0; r < 8; r++) acc += part8[r][d];
                G_g[i * D + d] = acc;
            }
        }
        gsync(bar++);
    }

    // ---- tail: block 127 computes out = y0 + (w@G)_{127} ----
    if (bid == T - 1) {
        int d = tid & 63, p = tid >> 6;
        float s = 0.0f;
        #pragma unroll
        for (int r = 0; r < 16; r++) {
            int i = p + r * 8;
            s += wfun(T - 1, i, dt) * __ldcg(&G_g[i * D + d]);
        }
        part8[p][d] = s;
        __syncthreads();
        if (p == 0) {
            float acc = z0[d];
            #pragma unroll
            for (int r = 0; r < 8; r++) acc += part8[r][d];
            out[d] = acc;
        }
    }
}

extern "C" void kernel_launch(void* const* d_in, const int* in_sizes, int n_in,
                              void* d_out, int out_size) {
    const float* z0  = (const float*)d_in[0];
    const float* t   = (const float*)d_in[1];
    const float* W1  = (const float*)d_in[2];
    const float* b1  = (const float*)d_in[3];
    const float* W2  = (const float*)d_in[4];
    const float* b2  = (const float*)d_in[5];
    const float* Wk1 = (const float*)d_in[6];
    const float* bk1 = (const float*)d_in[7];
    const float* Wk2 = (const float*)d_in[8];
    const float* bk2 = (const float*)d_in[9];
    float* out = (float*)d_out;

    static int attr_done = 0;
    if (!attr_done) {
        cudaFuncSetAttribute(mega, cudaFuncAttributeMaxDynamicSharedMemorySize, SMEM_BYTES);
        attr_done = 1;
    }
    mega<<<NB, NT, SMEM_BYTES>>>(z0, t, W1, b1, W2, b2, Wk1, bk1, Wk2, bk2, out);
}